// round 1
// baseline (speedup 1.0000x reference)
#include <cuda_runtime.h>

// ---------------------------------------------------------------------------
// ParallelBrainWithAdaptiveInhibition
//
// Per step t:
//   pot = (pot + sign*post_prev)*DECAY + noise[t] + (t==0)*ext
//   fired = pot >= th ; th = clip(th + fired*0.5 - 0.1, 1, 100)
//   post = segment_sum(fired[i]*weights[i,k] -> connections[i,k])
// Output: pot + sign*post  (after last step)
//
// Key optimization: scatter work is proportional to the number of FIRED
// neurons. We keep a per-neuron fired flag; the scatter kernel (warp-per-
// neuron) reads one flag and skips the 500-edge loop when 0. With this
// dataset nothing ever fires, so the heavy path costs ~one flag read per
// neuron per step. The atomicAdd path remains for general correctness.
// ---------------------------------------------------------------------------

#define MAX_N 100000

__device__ float g_pot [MAX_N];
__device__ float g_th  [MAX_N];
__device__ float g_post[MAX_N];
__device__ int   g_fired[MAX_N];

__global__ void update_kernel(const float* __restrict__ ext,
                              const float* __restrict__ inhib,
                              const float* __restrict__ noise_t,  // noise + t*n
                              const float* __restrict__ pot0,
                              const float* __restrict__ th0,
                              int n, int is_first)
{
    int i = blockIdx.x * blockDim.x + threadIdx.x;
    if (i >= n) return;

    float pot  = is_first ? pot0[i] : g_pot[i];
    float th   = is_first ? th0[i]  : g_th[i];
    float post = is_first ? 0.0f    : g_post[i];
    float sg   = 1.0f - 2.0f * inhib[i];

    // apply previous step's scatter, then this step's decay + noise (+ ext at t0)
    pot = (pot + sg * post) * 0.95f + noise_t[i];
    if (is_first) pot += ext[i];

    g_post[i] = 0.0f;                      // prep accumulator for this step's scatter

    int fired = (pot >= th) ? 1 : 0;
    g_fired[i] = fired;

    th = th + (fired ? 0.5f : 0.0f) - 0.1f;
    th = fminf(fmaxf(th, 1.0f), 100.0f);

    g_pot[i] = pot;
    g_th[i]  = th;
}

// Warp-per-neuron scatter. Reads one flag per neuron; only fired neurons
// stream their 500 coalesced (weight, connection) pairs and atomicAdd into
// g_post. With zero firers this kernel is a flag scan (~100k loads).
__global__ void scatter_kernel(const float* __restrict__ weights,
                               const int*   __restrict__ conn,
                               int n, int k)
{
    int gtid   = blockIdx.x * blockDim.x + threadIdx.x;
    int warp   = gtid >> 5;
    int lane   = gtid & 31;
    int nwarps = (gridDim.x * blockDim.x) >> 5;

    for (int i = warp; i < n; i += nwarps) {
        if (g_fired[i]) {
            const float* w = weights + (long long)i * k;
            const int*   c = conn    + (long long)i * k;
            for (int e = lane; e < k; e += 32) {
                atomicAdd(&g_post[c[e]], w[e]);
            }
        }
    }
}

__global__ void final_kernel(const float* __restrict__ inhib,
                             float* __restrict__ out, int n)
{
    int i = blockIdx.x * blockDim.x + threadIdx.x;
    if (i >= n) return;
    float sg = 1.0f - 2.0f * inhib[i];
    out[i]   = g_pot[i] + sg * g_post[i];
    g_post[i] = 0.0f;                      // reset scratch -> deterministic replays
}

extern "C" void kernel_launch(void* const* d_in, const int* in_sizes, int n_in,
                              void* d_out, int out_size)
{
    const float* ext     = (const float*)d_in[0];
    const float* weights = (const float*)d_in[1];
    const int*   conn    = (const int*)  d_in[2];
    const float* inhib   = (const float*)d_in[3];
    const float* noise   = (const float*)d_in[4];
    const float* pot0    = (const float*)d_in[5];
    const float* th0     = (const float*)d_in[6];
    // d_in[7] = steps scalar (device); derive host-side instead (graph-safe):

    int n     = in_sizes[0];
    int k     = in_sizes[1] / n;
    int steps = in_sizes[4] / n;

    int nb = (n + 255) / 256;

    for (int t = 0; t < steps; t++) {
        update_kernel<<<nb, 256>>>(ext, inhib, noise + (size_t)t * n,
                                   pot0, th0, n, (t == 0) ? 1 : 0);
        scatter_kernel<<<512, 256>>>(weights, conn, n, k);
    }
    final_kernel<<<nb, 256>>>(inhib, (float*)d_out, n);
}

// round 2
// speedup vs baseline: 2.3856x; 2.3856x over previous
#include <cuda_runtime.h>

// ---------------------------------------------------------------------------
// ParallelBrainWithAdaptiveInhibition — single persistent kernel.
//
// Per step t:
//   pot = (pot + sign*post_prev)*DECAY + noise[t] + (t==0)*ext
//   fired = pot >= th ; th = clip(th + fired*0.5 - 0.1, 1, 100)
//   post  = segment_sum(fired[i]*weights[i,:] scattered to connections[i,:])
// Output after last step: pot + sign*post
//
// All 10 steps run inside ONE kernel launch. pot/th/sign live in registers
// (one thread per neuron). Steps are separated by a hand-rolled grid barrier
// (98 blocks, guaranteed single-wave co-resident). A monotonic global fire
// counter lets every block detect "no new fires this step" and skip both the
// scatter phase and its trailing barrier — with this dataset no neuron ever
// crosses threshold 50, so each step costs one barrier + elementwise math.
// The atomic-scatter path remains fully functional for general inputs.
// ---------------------------------------------------------------------------

#define MAX_N 100000

__device__ float    g_post [MAX_N];   // zero-init; self-resetting across replays
__device__ int      g_fired[MAX_N];
__device__ volatile unsigned g_gen;   // barrier generation (monotonic)
__device__ unsigned g_arrive;         // barrier arrival counter
__device__ unsigned g_total;          // monotonic total-fires counter (reset at end)

__device__ __forceinline__ void grid_barrier(int nblocks)
{
    __syncthreads();
    if (threadIdx.x == 0) {
        __threadfence();                       // make this block's writes visible
        unsigned gen = g_gen;                  // read BEFORE arriving
        if (atomicAdd(&g_arrive, 1u) == (unsigned)(nblocks - 1)) {
            g_arrive = 0;
            __threadfence();
            g_gen = gen + 1u;                  // release
        } else {
            while (g_gen == gen) { }           // spin (volatile read, L2)
        }
        __threadfence();                       // acquire others' writes
    }
    __syncthreads();
}

__global__ void __launch_bounds__(1024, 1)
brain_kernel(const float* __restrict__ ext,
             const float* __restrict__ weights,
             const int*   __restrict__ conn,
             const float* __restrict__ inhib,
             const float* __restrict__ noise,
             const float* __restrict__ pot0,
             const float* __restrict__ th0,
             float* __restrict__ out,
             int n, int k, int steps, int nblocks)
{
    const int i      = blockIdx.x * blockDim.x + threadIdx.x;
    const bool alive = (i < n);

    float pot = 0.f, th = 0.f, sg = 0.f;
    if (alive) {
        pot = pot0[i];
        th  = th0[i];
        sg  = 1.0f - 2.0f * inhib[i];
    }

    unsigned prev_total = 0;     // g_total is 0 at every launch (reset at end)
    bool post_dirty = false;     // true iff g_post may hold nonzero values

    for (int t = 0; t < steps; t++) {
        int fired = 0;
        if (alive) {
            float post = 0.0f;
            if (post_dirty) {            // previous step scattered something
                post = g_post[i];
                g_post[i] = 0.0f;        // reset before this step's scatter
            }
            pot = (pot + sg * post) * 0.95f + noise[(size_t)t * n + i];
            if (t == 0) pot += ext[i];

            fired = (pot >= th) ? 1 : 0;
            g_fired[i] = fired;

            th = th + (fired ? 0.5f : 0.0f) - 0.1f;
            th = fminf(fmaxf(th, 1.0f), 100.0f);
        }

        // block-level fired count; leader accumulates into monotonic g_total
        int bcnt = __syncthreads_count(fired);
        if (threadIdx.x == 0 && bcnt > 0) atomicAdd(&g_total, (unsigned)bcnt);

        grid_barrier(nblocks);           // fired flags + g_post resets visible

        unsigned tot = *((volatile unsigned*)&g_total);
        bool new_fires = (tot != prev_total);
        prev_total = tot;

        if (new_fires) {
            // warp-per-neuron scatter over fired neurons (general path)
            int gtid   = blockIdx.x * blockDim.x + threadIdx.x;
            int warp   = gtid >> 5;
            int lane   = gtid & 31;
            int nwarps = (nblocks * (int)blockDim.x) >> 5;
            for (int j = warp; j < n; j += nwarps) {
                if (g_fired[j]) {
                    const float* w = weights + (long long)j * k;
                    const int*   c = conn    + (long long)j * k;
                    for (int e = lane; e < k; e += 32)
                        atomicAdd(&g_post[c[e]], w[e]);
                }
            }
            grid_barrier(nblocks);       // scatter complete before next update
            post_dirty = true;
        } else {
            post_dirty = false;
        }
    }

    // final barrier: protects g_total reset against blocks still reading it
    grid_barrier(nblocks);

    if (alive) {
        float post = 0.0f;
        if (post_dirty) {
            post = g_post[i];
            g_post[i] = 0.0f;            // scratch clean for next graph replay
        }
        out[i] = pot + sg * post;
    }
    if (blockIdx.x == 0 && threadIdx.x == 0) g_total = 0u;
}

extern "C" void kernel_launch(void* const* d_in, const int* in_sizes, int n_in,
                              void* d_out, int out_size)
{
    const float* ext     = (const float*)d_in[0];
    const float* weights = (const float*)d_in[1];
    const int*   conn    = (const int*)  d_in[2];
    const float* inhib   = (const float*)d_in[3];
    const float* noise   = (const float*)d_in[4];
    const float* pot0    = (const float*)d_in[5];
    const float* th0     = (const float*)d_in[6];

    int n     = in_sizes[0];
    int k     = in_sizes[1] / n;
    int steps = in_sizes[4] / n;

    int nb = (n + 1023) / 1024;   // 98 blocks for n=100000 -> single wave on 148 SMs

    brain_kernel<<<nb, 1024>>>(ext, weights, conn, inhib, noise, pot0, th0,
                               (float*)d_out, n, k, steps, nb);
}